// round 4
// baseline (speedup 1.0000x reference)
#include <cuda_runtime.h>
#include <math.h>

#define BB 4
#define NN 50000
#define KK 128
#define NP (KK/2)                      // 64 packed gaussian pairs
#define GD 128
#define TPB 128
#define PPT 4                          // points per thread
#define PPB (TPB * PPT)                // 512 points per block
#define NBLK ((NN + PPB - 1) / PPB)    // 98
#define TOTAL_BLK (BB * NBLK)          // 392

__device__ float        g_partial[TOTAL_BLK];
__device__ unsigned int g_count = 0;

__device__ __forceinline__ float ex2f(float x) {
    float y; asm("ex2.approx.ftz.f32 %0, %1;" : "=f"(y) : "f"(x)); return y;
}

union F2U { float2 f; unsigned long long u; };

__device__ __forceinline__ float2 fma2(float2 a, float2 b, float2 c) {
    F2U A, B, C, D; A.f = a; B.f = b; C.f = c;
    asm("fma.rn.f32x2 %0, %1, %2, %3;" : "=l"(D.u) : "l"(A.u), "l"(B.u), "l"(C.u));
    return D.f;
}
__device__ __forceinline__ float2 add2(float2 a, float2 b) {
    F2U A, B, D; A.f = a; B.f = b;
    asm("add.rn.f32x2 %0, %1, %2;" : "=l"(D.u) : "l"(A.u), "l"(B.u));
    return D.f;
}
__device__ __forceinline__ float2 mul2(float2 a, float2 b) {
    F2U A, B, D; A.f = a; B.f = b;
    asm("mul.rn.f32x2 %0, %1, %2;" : "=l"(D.u) : "l"(A.u), "l"(B.u));
    return D.f;
}

// Pair-interleaved param layout (per gaussian pair p, lanes = even/odd k):
//  v0..2 = Rrel row0   v3  = -cx
//  v4..6 = Rrel row1   v7  = -cy
//  v8..10= Rrel row2   v11 = -cz
//  v12..14 = ct        v15 = a  (= -log2e / 2s^2)
//  v16 = lb (= log2(c^2))   v17 = pad
__global__ __launch_bounds__(TPB, 3)
void fused_kernel(const float* __restrict__ constants,
                  const float* __restrict__ scales,
                  const float* __restrict__ rot,
                  const float* __restrict__ centers,
                  const float* __restrict__ samples,
                  const float* __restrict__ grid,
                  const float* __restrict__ w2g,
                  float* __restrict__ out) {
    int b   = blockIdx.x / NBLK;
    int blk = blockIdx.x - b * NBLK;
    int bt  = (b + 1) & 3;
    int nbase = blk * PPB + threadIdx.x;

    __shared__ float spf[NP * 36];
    __shared__ float red[TPB];
    __shared__ bool  s_last;

    // ---- in-block precompute of per-(b,k) params (all 128 threads) ----
    {
        int k = threadIdx.x;
        const float* R  = rot + (size_t)(b  * KK + k) * 9;
        const float* Rt = rot + (size_t)(bt * KK + k) * 9;
        float v[18];
#pragma unroll
        for (int i = 0; i < 3; i++)
#pragma unroll
            for (int l = 0; l < 3; l++)
                v[i * 4 + l] = Rt[i*3+0]*R[l*3+0] + Rt[i*3+1]*R[l*3+1] + Rt[i*3+2]*R[l*3+2];
        const float* c  = centers + (size_t)(b  * KK + k) * 3;
        const float* ct = centers + (size_t)(bt * KK + k) * 3;
        v[3]  = -c[0];  v[7]  = -c[1];  v[11] = -c[2];
        v[12] = ct[0];  v[13] = ct[1];  v[14] = ct[2];
        float s  = scales[b * KK + k];
        float cc = constants[b * KK + k];
        v[15] = -1.4426950408889634f / (2.0f * s * s);
        v[16] = log2f(cc * cc);
        v[17] = 0.0f;
        int p = k >> 1, lane = k & 1;
        float* dst = spf + p * 36 + lane;
#pragma unroll
        for (int vi = 0; vi < 18; vi++) dst[2 * vi] = v[vi];
    }
    __syncthreads();

    bool   ok[PPT];
    float2 px2[PPT], py2[PPT], pz2[PPT];
    float2 ws[PPT], ax[PPT], ay[PPT], az[PPT];
#pragma unroll
    for (int t = 0; t < PPT; t++) {
        int n = nbase + t * TPB;
        ok[t] = (n < NN);
        float px = 0.f, py = 0.f, pz = 0.f;
        if (ok[t]) {
            const float* s6 = samples + (size_t)(b * NN + n) * 6;
            px = s6[0]; py = s6[1]; pz = s6[2];
        }
        px2[t] = make_float2(px, px);
        py2[t] = make_float2(py, py);
        pz2[t] = make_float2(pz, pz);
        ws[t] = make_float2(0.f, 0.f);
        ax[t] = ws[t]; ay[t] = ws[t]; az[t] = ws[t];
    }

    const float4* sp4 = (const float4*)spf;
    for (int p = 0; p < NP; p++) {
        float4 f0 = sp4[p*9+0], f1 = sp4[p*9+1], f2 = sp4[p*9+2];
        float4 f3 = sp4[p*9+3], f4 = sp4[p*9+4], f5 = sp4[p*9+5];
        float4 f6 = sp4[p*9+6], f7 = sp4[p*9+7], f8 = sp4[p*9+8];
        float2 q0  = make_float2(f0.x, f0.y), q1  = make_float2(f0.z, f0.w);
        float2 q2  = make_float2(f1.x, f1.y), q3  = make_float2(f1.z, f1.w);
        float2 q4  = make_float2(f2.x, f2.y), q5  = make_float2(f2.z, f2.w);
        float2 q6  = make_float2(f3.x, f3.y), q7  = make_float2(f3.z, f3.w);
        float2 q8  = make_float2(f4.x, f4.y), q9  = make_float2(f4.z, f4.w);
        float2 q10 = make_float2(f5.x, f5.y), q11 = make_float2(f5.z, f5.w);
        float2 q12 = make_float2(f6.x, f6.y), q13 = make_float2(f6.z, f6.w);
        float2 q14 = make_float2(f7.x, f7.y), q15 = make_float2(f7.z, f7.w);
        float2 q16 = make_float2(f8.x, f8.y);

#pragma unroll
        for (int t = 0; t < PPT; t++) {
            float2 dx = add2(px2[t], q3);
            float2 dy = add2(py2[t], q7);
            float2 dz = add2(pz2[t], q11);
            float2 d2 = fma2(dz, dz, fma2(dy, dy, mul2(dx, dx)));
            float2 arg = fma2(d2, q15, q16);
            float2 w;
            w.x = ex2f(arg.x);
            w.y = ex2f(arg.y);
            float2 tx = fma2(q0, dx, fma2(q1, dy, fma2(q2,  dz, q12)));
            float2 ty = fma2(q4, dx, fma2(q5, dy, fma2(q6,  dz, q13)));
            float2 tz = fma2(q8, dx, fma2(q9, dy, fma2(q10, dz, q14)));
            ws[t] = add2(ws[t], w);
            ax[t] = fma2(w, tx, ax[t]);
            ay[t] = fma2(w, ty, ay[t]);
            az[t] = fma2(w, tz, az[t]);
        }
    }

    const float* M = w2g + bt * 16;
    const float* g = grid + (size_t)bt * GD * GD * GD;
    const float dm = (float)(GD - 1);

    float val = 0.0f;
#pragma unroll
    for (int t = 0; t < PPT; t++) {
        if (!ok[t]) continue;
        float wsv = ws[t].x + ws[t].y;
        float inv = 1.0f / wsv;
        float bx = (ax[t].x + ax[t].y) * inv;
        float by = (ay[t].x + ay[t].y) * inv;
        float bz = (az[t].x + az[t].y) * inv;

        float gx = M[0]*bx + M[1]*by + M[2]*bz  + M[3];
        float gy = M[4]*bx + M[5]*by + M[6]*bz  + M[7];
        float gz = M[8]*bx + M[9]*by + M[10]*bz + M[11];

        float nx = 2.0f * (gx / dm) - 1.0f;
        float ny = 2.0f * (gy / dm) - 1.0f;
        float nz = 2.0f * (gz / dm) - 1.0f;

        float x = fminf(fmaxf((nx + 1.0f) * 0.5f * dm, 0.0f), dm);
        float y = fminf(fmaxf((ny + 1.0f) * 0.5f * dm, 0.0f), dm);
        float z = fminf(fmaxf((nz + 1.0f) * 0.5f * dm, 0.0f), dm);

        float x0f = floorf(x), y0f = floorf(y), z0f = floorf(z);
        float fx = x - x0f, fy = y - y0f, fz = z - z0f;
        int x0 = (int)x0f, y0 = (int)y0f, z0 = (int)z0f;
        int x1 = min(x0 + 1, GD - 1);
        int y1 = min(y0 + 1, GD - 1);
        int z1 = min(z0 + 1, GD - 1);

        int zy00 = (z0 * GD + y0) * GD;
        int zy01 = (z0 * GD + y1) * GD;
        int zy10 = (z1 * GD + y0) * GD;
        int zy11 = (z1 * GD + y1) * GD;
        float c000 = __ldg(g + zy00 + x0);
        float c001 = __ldg(g + zy00 + x1);
        float c010 = __ldg(g + zy01 + x0);
        float c011 = __ldg(g + zy01 + x1);
        float c100 = __ldg(g + zy10 + x0);
        float c101 = __ldg(g + zy10 + x1);
        float c110 = __ldg(g + zy11 + x0);
        float c111 = __ldg(g + zy11 + x1);

        float c00 = c000 + (c001 - c000) * fx;
        float c01 = c010 + (c011 - c010) * fx;
        float c10 = c100 + (c101 - c100) * fx;
        float c11 = c110 + (c111 - c110) * fx;
        float c0  = c00 + (c01 - c00) * fy;
        float c1  = c10 + (c11 - c10) * fy;
        float sdf = c0 + (c1 - c0) * fz;
        val += sdf * sdf;
    }

    // ---- deterministic block reduction ----
    red[threadIdx.x] = val;
    __syncthreads();
#pragma unroll
    for (int s = TPB / 2; s > 0; s >>= 1) {
        if (threadIdx.x < s) red[threadIdx.x] += red[threadIdx.x + s];
        __syncthreads();
    }
    if (threadIdx.x == 0) {
        g_partial[blockIdx.x] = red[0];
        __threadfence();
        unsigned int t = atomicAdd(&g_count, 1u);
        s_last = (t == TOTAL_BLK - 1);
    }
    __syncthreads();

    // ---- last block finalizes (fixed-order, deterministic) ----
    if (s_last) {
        float s = 0.0f;
        for (int i = threadIdx.x; i < TOTAL_BLK; i += TPB) s += g_partial[i];
        red[threadIdx.x] = s;
        __syncthreads();
#pragma unroll
        for (int st = TPB / 2; st > 0; st >>= 1) {
            if (threadIdx.x < st) red[threadIdx.x] += red[threadIdx.x + st];
            __syncthreads();
        }
        if (threadIdx.x == 0) {
            out[0] = red[0] * (1.0f / (float)NN);
            g_count = 0;   // reset for next graph replay
        }
    }
}

extern "C" void kernel_launch(void* const* d_in, const int* in_sizes, int n_in,
                              void* d_out, int out_size) {
    const float* constants = (const float*)d_in[0];   // (B,K)
    const float* scales    = (const float*)d_in[1];   // (B,K)
    const float* rotations = (const float*)d_in[2];   // (B,K,3,3)
    const float* centers   = (const float*)d_in[3];   // (B,K,3)
    const float* samples   = (const float*)d_in[4];   // (B,N,6)
    const float* grid      = (const float*)d_in[5];   // (B,GD,GD,GD)
    const float* w2g       = (const float*)d_in[6];   // (B,4,4)
    float* out = (float*)d_out;

    fused_kernel<<<TOTAL_BLK, TPB>>>(constants, scales, rotations, centers,
                                     samples, grid, w2g, out);
}

// round 6
// speedup vs baseline: 1.0609x; 1.0609x over previous
#include <cuda_runtime.h>
#include <math.h>

#define BB 4
#define NN 50000
#define KK 128
#define NP (KK/2)                      // 64 packed gaussian pairs
#define GD 128
#define TPB 128
#define PPT 4                          // point slots per thread
#define CHUNK 451                      // points per block (111*451 >= 50000)
#define NBLK 111
#define TOTAL_BLK (BB * NBLK)          // 444 = 3 CTAs per SM exactly

__device__ float        g_partial[TOTAL_BLK];
__device__ unsigned int g_count = 0;

__device__ __forceinline__ float ex2f(float x) {
    float y; asm("ex2.approx.ftz.f32 %0, %1;" : "=f"(y) : "f"(x)); return y;
}

union F2U { float2 f; unsigned long long u; };

__device__ __forceinline__ float2 fma2(float2 a, float2 b, float2 c) {
    F2U A, B, C, D; A.f = a; B.f = b; C.f = c;
    asm("fma.rn.f32x2 %0, %1, %2, %3;" : "=l"(D.u) : "l"(A.u), "l"(B.u), "l"(C.u));
    return D.f;
}
__device__ __forceinline__ float2 add2(float2 a, float2 b) {
    F2U A, B, D; A.f = a; B.f = b;
    asm("add.rn.f32x2 %0, %1, %2;" : "=l"(D.u) : "l"(A.u), "l"(B.u));
    return D.f;
}

// Pair-interleaved param layout (per gaussian pair p, lanes = even/odd k), 18 float2:
//  v0..2  = Rrel row0    v3  = ex   (= -2a*cx)
//  v4..6  = Rrel row1    v7  = ey
//  v8..10 = Rrel row2    v11 = ez
//  v12..14= u (= ct - Rrel*c)
//  v15 = a (= -log2e/(2 s^2))   v16 = f (= a*|c|^2 + log2(c^2))   v17 = pad
__global__ __launch_bounds__(TPB, 3)
void fused_kernel(const float* __restrict__ constants,
                  const float* __restrict__ scales,
                  const float* __restrict__ rot,
                  const float* __restrict__ centers,
                  const float* __restrict__ samples,
                  const float* __restrict__ grid,
                  const float* __restrict__ w2g,
                  float* __restrict__ out) {
    int b   = blockIdx.x / NBLK;
    int blk = blockIdx.x - b * NBLK;
    int bt  = (b + 1) & 3;
    int base  = blk * CHUNK;
    int limit = min(CHUNK, NN - base);   // valid point slots in this block

    __shared__ float spf[NP * 36];
    __shared__ float red[TPB];
    __shared__ bool  s_last;

    // ---- in-block precompute of per-(b,k) params ----
    {
        int k = threadIdx.x;
        const float* R  = rot + (size_t)(b  * KK + k) * 9;
        const float* Rt = rot + (size_t)(bt * KK + k) * 9;
        float Rr[9];
#pragma unroll
        for (int i = 0; i < 3; i++)
#pragma unroll
            for (int l = 0; l < 3; l++)
                Rr[i*3+l] = Rt[i*3+0]*R[l*3+0] + Rt[i*3+1]*R[l*3+1] + Rt[i*3+2]*R[l*3+2];
        const float* c  = centers + (size_t)(b  * KK + k) * 3;
        const float* ct = centers + (size_t)(bt * KK + k) * 3;
        float cx = c[0], cy = c[1], cz = c[2];
        float s  = scales[b * KK + k];
        float cc = constants[b * KK + k];
        float a  = -1.4426950408889634f / (2.0f * s * s);
        float lb = log2f(cc * cc);

        float v[18];
        v[0] = Rr[0]; v[1] = Rr[1]; v[2] = Rr[2];
        v[4] = Rr[3]; v[5] = Rr[4]; v[6] = Rr[5];
        v[8] = Rr[6]; v[9] = Rr[7]; v[10]= Rr[8];
        v[3]  = -2.0f * a * cx;
        v[7]  = -2.0f * a * cy;
        v[11] = -2.0f * a * cz;
        v[12] = ct[0] - (Rr[0]*cx + Rr[1]*cy + Rr[2]*cz);
        v[13] = ct[1] - (Rr[3]*cx + Rr[4]*cy + Rr[5]*cz);
        v[14] = ct[2] - (Rr[6]*cx + Rr[7]*cy + Rr[8]*cz);
        v[15] = a;
        v[16] = a * (cx*cx + cy*cy + cz*cz) + lb;
        v[17] = 0.0f;
        int p = k >> 1, lane = k & 1;
        float* dst = spf + p * 36 + lane;
#pragma unroll
        for (int vi = 0; vi < 18; vi++) dst[2 * vi] = v[vi];
    }
    __syncthreads();

    bool   ok[PPT];
    float2 px2[PPT], py2[PPT], pz2[PPT], sp2[PPT];
    float2 ws[PPT], ax[PPT], ay[PPT], az[PPT];
#pragma unroll
    for (int t = 0; t < PPT; t++) {
        int slot = threadIdx.x + t * TPB;
        ok[t] = (slot < limit);
        float px = 0.f, py = 0.f, pz = 0.f;
        if (ok[t]) {
            const float* s6 = samples + (size_t)(b * NN + base + slot) * 6;
            px = s6[0]; py = s6[1]; pz = s6[2];
        }
        float sp = px*px + py*py + pz*pz;
        px2[t] = make_float2(px, px);
        py2[t] = make_float2(py, py);
        pz2[t] = make_float2(pz, pz);
        sp2[t] = make_float2(sp, sp);
        ws[t] = make_float2(0.f, 0.f);
        ax[t] = ws[t]; ay[t] = ws[t]; az[t] = ws[t];
    }

    const float4* sp4 = (const float4*)spf;
    for (int p = 0; p < NP; p++) {
        float4 f0 = sp4[p*9+0], f1 = sp4[p*9+1], f2 = sp4[p*9+2];
        float4 f3 = sp4[p*9+3], f4 = sp4[p*9+4], f5 = sp4[p*9+5];
        float4 f6 = sp4[p*9+6], f7 = sp4[p*9+7], f8 = sp4[p*9+8];
        float2 q0  = make_float2(f0.x, f0.y), q1  = make_float2(f0.z, f0.w);
        float2 q2  = make_float2(f1.x, f1.y), q3  = make_float2(f1.z, f1.w);
        float2 q4  = make_float2(f2.x, f2.y), q5  = make_float2(f2.z, f2.w);
        float2 q6  = make_float2(f3.x, f3.y), q7  = make_float2(f3.z, f3.w);
        float2 q8  = make_float2(f4.x, f4.y), q9  = make_float2(f4.z, f4.w);
        float2 q10 = make_float2(f5.x, f5.y), q11 = make_float2(f5.z, f5.w);
        float2 q12 = make_float2(f6.x, f6.y), q13 = make_float2(f6.z, f6.w);
        float2 q14 = make_float2(f7.x, f7.y), q15 = make_float2(f7.z, f7.w);
        float2 q16 = make_float2(f8.x, f8.y);

#pragma unroll
        for (int t = 0; t < PPT; t++) {
            float2 arg = fma2(q15, sp2[t],
                         fma2(q3, px2[t],
                         fma2(q7, py2[t],
                         fma2(q11, pz2[t], q16))));
            float2 w;
            w.x = ex2f(arg.x);
            w.y = ex2f(arg.y);
            float2 tx = fma2(q0, px2[t], fma2(q1, py2[t], fma2(q2,  pz2[t], q12)));
            float2 ty = fma2(q4, px2[t], fma2(q5, py2[t], fma2(q6,  pz2[t], q13)));
            float2 tz = fma2(q8, px2[t], fma2(q9, py2[t], fma2(q10, pz2[t], q14)));
            ws[t] = add2(ws[t], w);
            ax[t] = fma2(w, tx, ax[t]);
            ay[t] = fma2(w, ty, ay[t]);
            az[t] = fma2(w, tz, az[t]);
        }
    }

    const float* M = w2g + bt * 16;
    const float* g = grid + (size_t)bt * GD * GD * GD;
    const float dm = (float)(GD - 1);

    float val = 0.0f;
#pragma unroll
    for (int t = 0; t < PPT; t++) {
        if (!ok[t]) continue;
        float wsv = ws[t].x + ws[t].y;
        float inv = 1.0f / wsv;
        float bx = (ax[t].x + ax[t].y) * inv;
        float by = (ay[t].x + ay[t].y) * inv;
        float bz = (az[t].x + az[t].y) * inv;

        float gx = M[0]*bx + M[1]*by + M[2]*bz  + M[3];
        float gy = M[4]*bx + M[5]*by + M[6]*bz  + M[7];
        float gz = M[8]*bx + M[9]*by + M[10]*bz + M[11];

        float nx = 2.0f * (gx / dm) - 1.0f;
        float ny = 2.0f * (gy / dm) - 1.0f;
        float nz = 2.0f * (gz / dm) - 1.0f;

        float x = fminf(fmaxf((nx + 1.0f) * 0.5f * dm, 0.0f), dm);
        float y = fminf(fmaxf((ny + 1.0f) * 0.5f * dm, 0.0f), dm);
        float z = fminf(fmaxf((nz + 1.0f) * 0.5f * dm, 0.0f), dm);

        float x0f = floorf(x), y0f = floorf(y), z0f = floorf(z);
        float fx = x - x0f, fy = y - y0f, fz = z - z0f;
        int x0 = (int)x0f, y0 = (int)y0f, z0 = (int)z0f;
        int x1 = min(x0 + 1, GD - 1);
        int y1 = min(y0 + 1, GD - 1);
        int z1 = min(z0 + 1, GD - 1);

        int zy00 = (z0 * GD + y0) * GD;
        int zy01 = (z0 * GD + y1) * GD;
        int zy10 = (z1 * GD + y0) * GD;
        int zy11 = (z1 * GD + y1) * GD;
        float c000 = __ldg(g + zy00 + x0);
        float c001 = __ldg(g + zy00 + x1);
        float c010 = __ldg(g + zy01 + x0);
        float c011 = __ldg(g + zy01 + x1);
        float c100 = __ldg(g + zy10 + x0);
        float c101 = __ldg(g + zy10 + x1);
        float c110 = __ldg(g + zy11 + x0);
        float c111 = __ldg(g + zy11 + x1);

        float c00 = c000 + (c001 - c000) * fx;
        float c01 = c010 + (c011 - c010) * fx;
        float c10 = c100 + (c101 - c100) * fx;
        float c11 = c110 + (c111 - c110) * fx;
        float c0  = c00 + (c01 - c00) * fy;
        float c1  = c10 + (c11 - c10) * fy;
        float sdf = c0 + (c1 - c0) * fz;
        val += sdf * sdf;
    }

    // ---- deterministic block reduction ----
    red[threadIdx.x] = val;
    __syncthreads();
#pragma unroll
    for (int s = TPB / 2; s > 0; s >>= 1) {
        if (threadIdx.x < s) red[threadIdx.x] += red[threadIdx.x + s];
        __syncthreads();
    }
    if (threadIdx.x == 0) {
        g_partial[blockIdx.x] = red[0];
        __threadfence();
        unsigned int t = atomicAdd(&g_count, 1u);
        s_last = (t == TOTAL_BLK - 1);
    }
    __syncthreads();

    // ---- last block finalizes (fixed-order, deterministic) ----
    if (s_last) {
        float s = 0.0f;
        for (int i = threadIdx.x; i < TOTAL_BLK; i += TPB) s += g_partial[i];
        red[threadIdx.x] = s;
        __syncthreads();
#pragma unroll
        for (int st = TPB / 2; st > 0; st >>= 1) {
            if (threadIdx.x < st) red[threadIdx.x] += red[threadIdx.x + st];
            __syncthreads();
        }
        if (threadIdx.x == 0) {
            out[0] = red[0] * (1.0f / (float)NN);
            g_count = 0;   // reset for next graph replay
        }
    }
}

extern "C" void kernel_launch(void* const* d_in, const int* in_sizes, int n_in,
                              void* d_out, int out_size) {
    const float* constants = (const float*)d_in[0];   // (B,K)
    const float* scales    = (const float*)d_in[1];   // (B,K)
    const float* rotations = (const float*)d_in[2];   // (B,K,3,3)
    const float* centers   = (const float*)d_in[3];   // (B,K,3)
    const float* samples   = (const float*)d_in[4];   // (B,N,6)
    const float* grid      = (const float*)d_in[5];   // (B,GD,GD,GD)
    const float* w2g       = (const float*)d_in[6];   // (B,4,4)
    float* out = (float*)d_out;

    fused_kernel<<<TOTAL_BLK, TPB>>>(constants, scales, rotations, centers,
                                     samples, grid, w2g, out);
}